// round 6
// baseline (speedup 1.0000x reference)
#include <cuda_runtime.h>
#include <math.h>

#define BN 8192
#define FN 8192
#define DN 1024
#define H1N 256
#define H2N 64
#define NZC 102
#define CAP 96
#define GWIDTH 0.11f
#define RPB 32            /* rows per K5 block */
#define NPAIR (RPB/2)

// ---------------- scratch (device globals; no allocations allowed) ----------
__device__ float g_a1[BN * H1N];     // pre-BN activations layer 1
__device__ float g_a2[BN * H2N];     // pre-BN activations layer 2
__device__ float g_sc1[H1N], g_sh1[H1N];
__device__ float g_sc2[H2N], g_sh2[H2N];
__device__ double g_ps[64 * 256], g_pq[64 * 256];   // stats partials
__device__ int   g_ind[BN];          // final argmax per row

// ---------------- packed f32x2 helpers --------------------------------------
__device__ __forceinline__ void fma2(unsigned long long &d,
                                     unsigned long long a, unsigned long long b) {
    asm("fma.rn.f32x2 %0, %1, %2, %0;" : "+l"(d) : "l"(a), "l"(b));
}
__device__ __forceinline__ unsigned long long packdup(float w) {
    unsigned long long r;
    asm("mov.b64 %0, {%1, %1};" : "=l"(r) : "f"(w));
    return r;
}
__device__ __forceinline__ unsigned long long pack2(float x, float y) {
    unsigned long long r;
    asm("mov.b64 %0, {%1, %2};" : "=l"(r) : "f"(x), "f"(y));
    return r;
}
__device__ __forceinline__ void unpack2(unsigned long long v, float &lo, float &hi) {
    asm("mov.b64 {%0, %1}, %2;" : "=f"(lo), "=f"(hi) : "l"(v));
}

// ---------------- threefry-2x32, key = (0, 42) ------------------------------
__device__ __forceinline__ unsigned int jax_bits(unsigned int j) {
    const unsigned int k0 = 0u, k1 = 42u;
    const unsigned int k2 = 0x1BD11BDAu ^ k0 ^ k1;
    unsigned int x0 = 0u + k0, x1 = j + k1;
#define TF_R(r) { x0 += x1; x1 = (x1 << (r)) | (x1 >> (32 - (r))); x1 ^= x0; }
    TF_R(13) TF_R(15) TF_R(26) TF_R(6)
    x0 += k1; x1 += k2 + 1u;
    TF_R(17) TF_R(29) TF_R(16) TF_R(24)
    x0 += k2; x1 += k0 + 2u;
    TF_R(13) TF_R(15) TF_R(26) TF_R(6)
    x0 += k0; x1 += k1 + 3u;
    TF_R(17) TF_R(29) TF_R(16) TF_R(24)
    x0 += k1; x1 += k2 + 4u;
    TF_R(13) TF_R(15) TF_R(26) TF_R(6)
    x0 += k2; x1 += k0 + 5u;
#undef TF_R
    return x0 ^ x1;   // partitionable 32-bit: bits1 ^ bits2
}

// reference-matched gumbel: libdevice logf, no FMA contraction
__device__ __forceinline__ float gumbel_ref(unsigned int b) {
    float u = __uint_as_float((b >> 9) | 0x3F800000u) - 1.0f;   // [0,1)
    float U = __fmul_rn(0.001f, u);
    float t = __fadd_rn(U, 0.001f);          // [0.001, 0.002)
    float l1 = logf(t);
    float a  = __fadd_rn(-l1, 0.001f);       // (6.2156, 6.9088]
    return -logf(a);                          // [-1.93285, -1.82711]
}

// order-preserving float<->uint encoding (atomicMax on floats, any sign)
__device__ __forceinline__ unsigned int encf(float f) {
    unsigned int u = __float_as_uint(f);
    return (u & 0x80000000u) ? ~u : (u | 0x80000000u);
}
__device__ __forceinline__ float decf(unsigned int e) {
    unsigned int u = (e & 0x80000000u) ? (e ^ 0x80000000u) : ~e;
    return __uint_as_float(u);
}

// ---------------- K1: a1 = concat(x,y) @ W1 + b1 ----------------------------
__global__ __launch_bounds__(256) void k1_gemm1(const float* __restrict__ x,
                                                const float* __restrict__ y,
                                                const float* __restrict__ W1,
                                                const float* __restrict__ b1) {
    __shared__ float zs[8][NZC];
    const int rb = blockIdx.x * 8;
    const int tid = threadIdx.x;
    for (int i = tid; i < 8 * NZC; i += 256) {
        int r = i / NZC, c = i % NZC;
        zs[r][c] = (c < 100) ? x[(rb + r) * 100 + c] : y[(rb + r) * 2 + (c - 100)];
    }
    __syncthreads();
    const int col = tid;
    float acc[8];
#pragma unroll
    for (int r = 0; r < 8; r++) acc[r] = 0.0f;
    for (int k = 0; k < NZC; k++) {
        float w = W1[k * 256 + col];
#pragma unroll
        for (int r = 0; r < 8; r++) acc[r] = fmaf(zs[r][k], w, acc[r]);
    }
    const float bb = b1[col];
#pragma unroll
    for (int r = 0; r < 8; r++) g_a1[(rb + r) * 256 + col] = acc[r] + bb;
}

// ---------------- stats stage 1: coalesced per-column double partials -------
__global__ __launch_bounds__(256) void kstats1(int which) {
    const float* a = which ? g_a2 : g_a1;
    const int tid = threadIdx.x, b = blockIdx.x;   // 64 blocks
    double s0 = 0.0, s1 = 0.0, q0 = 0.0, q1 = 0.0;
    const int rb = b * 128;
    if (which == 0) {            // 256 cols: col=tid, 128 rows
        for (int s = 0; s < 128; s += 2) {
            float v0 = a[(rb + s) * 256 + tid];
            float v1 = a[(rb + s + 1) * 256 + tid];
            s0 += (double)v0; q0 = fma((double)v0, (double)v0, q0);
            s1 += (double)v1; q1 = fma((double)v1, (double)v1, q1);
        }
    } else {                     // 64 cols: col=tid&63, 4 row-replicas
        const int col = tid & 63, j = tid >> 6;
        for (int s = 0; s < 32; s += 2) {
            float v0 = a[(rb + j + 4 * s) * 64 + col];
            float v1 = a[(rb + j + 4 * (s + 1)) * 64 + col];
            s0 += (double)v0; q0 = fma((double)v0, (double)v0, q0);
            s1 += (double)v1; q1 = fma((double)v1, (double)v1, q1);
        }
    }
    g_ps[b * 256 + tid] = s0 + s1;
    g_pq[b * 256 + tid] = q0 + q1;
}

// ---------------- stats stage 2: deterministic reduce -> scale/shift --------
__global__ void kstats2(int which, const float* __restrict__ gamma,
                        const float* __restrict__ beta) {
    const int c = threadIdx.x;   // ncols threads
    double sa = 0.0, sb = 0.0, qa = 0.0, qb = 0.0;
    if (which == 0) {
        for (int b = 0; b < 64; b += 2) {
            sa += g_ps[b * 256 + c];       qa += g_pq[b * 256 + c];
            sb += g_ps[(b + 1) * 256 + c]; qb += g_pq[(b + 1) * 256 + c];
        }
    } else {
        for (int b = 0; b < 64; b++) {
            sa += g_ps[b * 256 + 0 * 64 + c]; qa += g_pq[b * 256 + 0 * 64 + c];
            sb += g_ps[b * 256 + 1 * 64 + c]; qb += g_pq[b * 256 + 1 * 64 + c];
            sa += g_ps[b * 256 + 2 * 64 + c]; qa += g_pq[b * 256 + 2 * 64 + c];
            sb += g_ps[b * 256 + 3 * 64 + c]; qb += g_pq[b * 256 + 3 * 64 + c];
        }
    }
    double s = sa + sb, q = qa + qb;
    double mean = s / (double)BN;
    double var  = q / (double)BN - mean * mean;
    float rstd = (float)(1.0 / sqrt(var + 1e-5));
    float scale = gamma[c] * rstd;
    if (which == 0) { g_sc1[c] = scale; g_sh1[c] = beta[c] - (float)mean * scale; }
    else            { g_sc2[c] = scale; g_sh2[c] = beta[c] - (float)mean * scale; }
}

// ---------------- K3: a2 = relu(BN(a1)) @ W2 + b2 ---------------------------
__global__ __launch_bounds__(256) void k3_gemm2(const float* __restrict__ W2,
                                                const float* __restrict__ b2) {
    __shared__ float h1s[16][256];
    const int rb = blockIdx.x * 16;
    const int tid = threadIdx.x;
#pragma unroll 4
    for (int r = 0; r < 16; r++) {
        float v = g_a1[(rb + r) * 256 + tid] * g_sc1[tid] + g_sh1[tid];
        h1s[r][tid] = fmaxf(v, 0.0f);
    }
    __syncthreads();
    const int c  = tid & 63;
    const int rq = tid >> 6;
    float acc[4] = {0.f, 0.f, 0.f, 0.f};
    for (int k = 0; k < 256; k++) {
        float w = W2[k * 64 + c];
#pragma unroll
        for (int i = 0; i < 4; i++) acc[i] = fmaf(h1s[rq * 4 + i][k], w, acc[i]);
    }
#pragma unroll
    for (int i = 0; i < 4; i++)
        g_a2[(rb + rq * 4 + i) * 64 + c] = acc[i] + b2[c];
}

// ---------------- K5: fused logits GEMM (f32x2) + bounded-gumbel argmax -----
// 32 rows/block, row-pairs in packed fma.rn.f32x2 accumulators. Gumbel noise
// lies in [-1.93285, -1.82711] (width 0.1058): only logits within GWIDTH of
// the running row max can win; candidates get exact threefry+logf refine.
__global__ __launch_bounds__(256) void k5_argmax(const float* __restrict__ W3,
                                                 const float* __restrict__ b3) {
    __shared__ float h2s[RPB][64];
    __shared__ ulonglong2 hp[32][NPAIR];   // [kpair][rowpair]: {r0k0,r1k0},{r0k1,r1k1}
    __shared__ unsigned int smaxe[RPB];
    __shared__ int scnt[RPB];
    __shared__ int cand[RPB][CAP];
    __shared__ float wrv[8];
    __shared__ int   wrf[8];
    const int tid = threadIdx.x;
    const int wid = tid >> 5, lid = tid & 31;
    const int rb  = blockIdx.x * RPB;

    for (int i = tid; i < RPB * 64; i += 256) {
        int r = i >> 6, k = i & 63;
        float v = g_a2[(rb + r) * 64 + k] * g_sc2[k] + g_sh2[k];
        h2s[r][k] = fmaxf(v, 0.0f);
    }
    if (tid < RPB) { smaxe[tid] = encf(-1e30f); scnt[tid] = 0; }
    __syncthreads();
    for (int i = tid; i < 32 * NPAIR; i += 256) {
        int kp = i / NPAIR, p = i % NPAIR;
        hp[kp][p] = make_ulonglong2(
            pack2(h2s[2 * p][2 * kp],     h2s[2 * p + 1][2 * kp]),
            pack2(h2s[2 * p][2 * kp + 1], h2s[2 * p + 1][2 * kp + 1]));
    }
    __syncthreads();

    for (int f0 = 0; f0 < FN; f0 += 256) {
        const int f = f0 + tid;
        unsigned long long acc2[NPAIR];
#pragma unroll
        for (int p = 0; p < NPAIR; p++) acc2[p] = 0ull;
        const float* wp = W3 + f;
#pragma unroll 2
        for (int kp = 0; kp < 32; kp++) {
            unsigned long long wkk  = packdup(wp[(2 * kp) * FN]);
            unsigned long long wk1  = packdup(wp[(2 * kp + 1) * FN]);
#pragma unroll
            for (int p = 0; p < NPAIR; p++) {
                ulonglong2 hv = hp[kp][p];
                fma2(acc2[p], hv.x, wkk);
                fma2(acc2[p], hv.y, wk1);
            }
        }
        const float bf = b3[f];
        float accf[RPB];
#pragma unroll
        for (int p = 0; p < NPAIR; p++) {
            float lo, hi;
            unpack2(acc2[p], lo, hi);
            accf[2 * p] = lo + bf;
            accf[2 * p + 1] = hi + bf;
        }
        // phase 1: push row maxima
#pragma unroll
        for (int r = 0; r < RPB; r++) {
            unsigned int e = *(volatile unsigned int*)&smaxe[r];
            if (accf[r] > decf(e)) atomicMax(&smaxe[r], encf(accf[r]));
        }
        __syncthreads();
        // phase 2: append candidates vs running max (safe superset)
#pragma unroll
        for (int r = 0; r < RPB; r++) {
            unsigned int e = *(volatile unsigned int*)&smaxe[r];
            if (accf[r] > decf(e) - GWIDTH) {
                int pos = atomicAdd(&scnt[r], 1);
                if (pos < CAP) cand[r][pos] = f;
            }
        }
    }
    __syncthreads();

    // exact refine per row in the reference's (logits+g)/TEMP domain
    for (int r = 0; r < RPB; r++) {
        const int row = rb + r;
        const int c = scnt[r];
        float bestv = -1e30f;
        int   bestf = 0x7FFFFFFF;
        if (c <= CAP) {
            if (tid < c) {
                const int f = cand[r][tid];
                float dot = 0.0f;
#pragma unroll
                for (int k = 0; k < 64; k++)
                    dot = fmaf(h2s[r][k], W3[k * FN + f], dot);
                float logit = __fadd_rn(dot, b3[f]);
                float g = gumbel_ref(jax_bits((unsigned)row * 8192u + (unsigned)f));
                bestv = __fdiv_rn(__fadd_rn(logit, g), 0.1f);
                bestf = f;
            }
        } else {
            for (int f = tid; f < FN; f += 256) {
                float dot = 0.0f;
#pragma unroll
                for (int k = 0; k < 64; k++)
                    dot = fmaf(h2s[r][k], W3[k * FN + f], dot);
                float logit = __fadd_rn(dot, b3[f]);
                float g = gumbel_ref(jax_bits((unsigned)row * 8192u + (unsigned)f));
                float v = __fdiv_rn(__fadd_rn(logit, g), 0.1f);
                if (v > bestv || (v == bestv && f < bestf)) { bestv = v; bestf = f; }
            }
        }
        // warp shuffle reduce (max by v, tie -> smaller f)
#pragma unroll
        for (int off = 16; off > 0; off >>= 1) {
            float ov = __shfl_xor_sync(0xFFFFFFFFu, bestv, off);
            int   of = __shfl_xor_sync(0xFFFFFFFFu, bestf, off);
            if (ov > bestv || (ov == bestv && of < bestf)) { bestv = ov; bestf = of; }
        }
        if (lid == 0) { wrv[wid] = bestv; wrf[wid] = bestf; }
        __syncthreads();
        if (wid == 0) {
            float v = (lid < 8) ? wrv[lid] : -1e30f;
            int   fo = (lid < 8) ? wrf[lid] : 0x7FFFFFFF;
#pragma unroll
            for (int off = 4; off > 0; off >>= 1) {
                float ov = __shfl_xor_sync(0xFFFFFFFFu, v, off);
                int   of = __shfl_xor_sync(0xFFFFFFFFu, fo, off);
                if (ov > v || (ov == v && of < fo)) { v = ov; fo = of; }
            }
            if (lid == 0) g_ind[row] = fo;
        }
        __syncthreads();
    }
}

// ---------------- K7: out[row] = codebook[ind[row]] -------------------------
__global__ void k7_gather(const float* __restrict__ codebook, float* __restrict__ out) {
    const int row = blockIdx.x;
    const int ind = g_ind[row];
    const float4* src = reinterpret_cast<const float4*>(codebook + (size_t)ind * DN);
    float4* dst = reinterpret_cast<float4*>(out + (size_t)row * DN);
    dst[threadIdx.x] = src[threadIdx.x];  // 256 threads * 16B = 4KB row
}

// ---------------- launch ----------------------------------------------------
extern "C" void kernel_launch(void* const* d_in, const int* in_sizes, int n_in,
                              void* d_out, int out_size) {
    const float* x   = (const float*)d_in[0];
    const float* y   = (const float*)d_in[1];
    const float* W1  = (const float*)d_in[2];
    const float* b1  = (const float*)d_in[3];
    const float* g1  = (const float*)d_in[4];
    const float* be1 = (const float*)d_in[5];
    const float* W2  = (const float*)d_in[6];
    const float* b2  = (const float*)d_in[7];
    const float* g2  = (const float*)d_in[8];
    const float* be2 = (const float*)d_in[9];
    const float* W3  = (const float*)d_in[10];
    const float* b3  = (const float*)d_in[11];
    const float* cb  = (const float*)d_in[12];
    float* out = (float*)d_out;

    k1_gemm1<<<BN / 8, 256>>>(x, y, W1, b1);
    kstats1<<<64, 256>>>(0);
    kstats2<<<1, H1N>>>(0, g1, be1);
    k3_gemm2<<<BN / 16, 256>>>(W2, b2);
    kstats1<<<64, 256>>>(1);
    kstats2<<<1, H2N>>>(1, g2, be2);
    k5_argmax<<<BN / RPB, 256>>>(W3, b3);
    k7_gather<<<BN, 256>>>(cb, out);
}

// round 7
// speedup vs baseline: 1.6422x; 1.6422x over previous
#include <cuda_runtime.h>
#include <math.h>

#define BN 8192
#define FN 8192
#define DN 1024
#define H1N 256
#define H2N 64
#define NZC 102
#define CAP 192
#define MARGIN 0.125f

// ---------------- scratch (device globals; no allocations allowed) ----------
__device__ float g_a1[BN * H1N];
__device__ float g_a2[BN * H2N];
__device__ float g_sc1[H1N], g_sh1[H1N];
__device__ float g_sc2[H2N], g_sh2[H2N];
__device__ double g_ps[64 * 256], g_pq[64 * 256];
__device__ int   g_ind[BN];

// ---------------- threefry-2x32, key = (0, 42) ------------------------------
__device__ __forceinline__ unsigned int jax_bits(unsigned int j) {
    const unsigned int k0 = 0u, k1 = 42u;
    const unsigned int k2 = 0x1BD11BDAu ^ k0 ^ k1;
    unsigned int x0 = 0u + k0, x1 = j + k1;
#define TF_R(r) { x0 += x1; x1 = (x1 << (r)) | (x1 >> (32 - (r))); x1 ^= x0; }
    TF_R(13) TF_R(15) TF_R(26) TF_R(6)
    x0 += k1; x1 += k2 + 1u;
    TF_R(17) TF_R(29) TF_R(16) TF_R(24)
    x0 += k2; x1 += k0 + 2u;
    TF_R(13) TF_R(15) TF_R(26) TF_R(6)
    x0 += k0; x1 += k1 + 3u;
    TF_R(17) TF_R(29) TF_R(16) TF_R(24)
    x0 += k1; x1 += k2 + 4u;
    TF_R(13) TF_R(15) TF_R(26) TF_R(6)
    x0 += k2; x1 += k0 + 5u;
#undef TF_R
    return x0 ^ x1;   // partitionable 32-bit: bits1 ^ bits2
}

__device__ __forceinline__ float gumbel_ref(unsigned int b) {
    float u = __uint_as_float((b >> 9) | 0x3F800000u) - 1.0f;   // [0,1)
    float U = __fmul_rn(0.001f, u);
    float t = __fadd_rn(U, 0.001f);
    float l1 = logf(t);
    float a  = __fadd_rn(-l1, 0.001f);
    return -logf(a);                      // [-1.93285, -1.82711]
}

__device__ __forceinline__ unsigned int encf(float f) {
    unsigned int u = __float_as_uint(f);
    return (u & 0x80000000u) ? ~u : (u | 0x80000000u);
}
__device__ __forceinline__ float decf(unsigned int e) {
    unsigned int u = (e & 0x80000000u) ? (e ^ 0x80000000u) : ~e;
    return __uint_as_float(u);
}

// ---------------- tf32 helpers ----------------------------------------------
__device__ __forceinline__ unsigned cvt_tf32(float x) {
    unsigned u;
    asm("cvt.rna.tf32.f32 %0, %1;" : "=r"(u) : "f"(x));
    return u;
}
__device__ __forceinline__ float tf32f(float x) { return __uint_as_float(cvt_tf32(x)); }

__device__ __forceinline__ void mma_tf32(float* c, const unsigned* a,
                                         unsigned b0, unsigned b1) {
    asm("mma.sync.aligned.m16n8k8.row.col.f32.tf32.tf32.f32 "
        "{%0,%1,%2,%3},{%4,%5,%6,%7},{%8,%9},{%0,%1,%2,%3};"
        : "+f"(c[0]), "+f"(c[1]), "+f"(c[2]), "+f"(c[3])
        : "r"(a[0]), "r"(a[1]), "r"(a[2]), "r"(a[3]), "r"(b0), "r"(b1));
}

// ---------------- K1: a1 = concat(x,y) @ W1 + b1 ----------------------------
__global__ __launch_bounds__(256) void k1_gemm1(const float* __restrict__ x,
                                                const float* __restrict__ y,
                                                const float* __restrict__ W1,
                                                const float* __restrict__ b1) {
    __shared__ float zs[8][NZC];
    const int rb = blockIdx.x * 8;
    const int tid = threadIdx.x;
    for (int i = tid; i < 8 * NZC; i += 256) {
        int r = i / NZC, c = i % NZC;
        zs[r][c] = (c < 100) ? x[(rb + r) * 100 + c] : y[(rb + r) * 2 + (c - 100)];
    }
    __syncthreads();
    const int col = tid;
    float acc[8];
#pragma unroll
    for (int r = 0; r < 8; r++) acc[r] = 0.0f;
    for (int k = 0; k < NZC; k++) {
        float w = W1[k * 256 + col];
#pragma unroll
        for (int r = 0; r < 8; r++) acc[r] = fmaf(zs[r][k], w, acc[r]);
    }
    const float bb = b1[col];
#pragma unroll
    for (int r = 0; r < 8; r++) g_a1[(rb + r) * 256 + col] = acc[r] + bb;
}

// ---------------- stats stage 1 ---------------------------------------------
__global__ __launch_bounds__(256) void kstats1(int which) {
    const float* a = which ? g_a2 : g_a1;
    const int tid = threadIdx.x, b = blockIdx.x;
    double s0 = 0.0, s1 = 0.0, q0 = 0.0, q1 = 0.0;
    const int rb = b * 128;
    if (which == 0) {
        for (int s = 0; s < 128; s += 2) {
            float v0 = a[(rb + s) * 256 + tid];
            float v1 = a[(rb + s + 1) * 256 + tid];
            s0 += (double)v0; q0 = fma((double)v0, (double)v0, q0);
            s1 += (double)v1; q1 = fma((double)v1, (double)v1, q1);
        }
    } else {
        const int col = tid & 63, j = tid >> 6;
        for (int s = 0; s < 32; s += 2) {
            float v0 = a[(rb + j + 4 * s) * 64 + col];
            float v1 = a[(rb + j + 4 * (s + 1)) * 64 + col];
            s0 += (double)v0; q0 = fma((double)v0, (double)v0, q0);
            s1 += (double)v1; q1 = fma((double)v1, (double)v1, q1);
        }
    }
    g_ps[b * 256 + tid] = s0 + s1;
    g_pq[b * 256 + tid] = q0 + q1;
}

// ---------------- stats stage 2 ---------------------------------------------
__global__ void kstats2(int which, const float* __restrict__ gamma,
                        const float* __restrict__ beta) {
    const int c = threadIdx.x;
    double sa = 0.0, sb = 0.0, qa = 0.0, qb = 0.0;
    if (which == 0) {
        for (int b = 0; b < 64; b += 2) {
            sa += g_ps[b * 256 + c];       qa += g_pq[b * 256 + c];
            sb += g_ps[(b + 1) * 256 + c]; qb += g_pq[(b + 1) * 256 + c];
        }
    } else {
        for (int b = 0; b < 64; b++) {
            sa += g_ps[b * 256 + 0 * 64 + c]; qa += g_pq[b * 256 + 0 * 64 + c];
            sb += g_ps[b * 256 + 1 * 64 + c]; qb += g_pq[b * 256 + 1 * 64 + c];
            sa += g_ps[b * 256 + 2 * 64 + c]; qa += g_pq[b * 256 + 2 * 64 + c];
            sb += g_ps[b * 256 + 3 * 64 + c]; qb += g_pq[b * 256 + 3 * 64 + c];
        }
    }
    double s = sa + sb, q = qa + qb;
    double mean = s / (double)BN;
    double var  = q / (double)BN - mean * mean;
    float rstd = (float)(1.0 / sqrt(var + 1e-5));
    float scale = gamma[c] * rstd;
    if (which == 0) { g_sc1[c] = scale; g_sh1[c] = beta[c] - (float)mean * scale; }
    else            { g_sc2[c] = scale; g_sh2[c] = beta[c] - (float)mean * scale; }
}

// ---------------- K3: a2 = relu(BN(a1)) @ W2 + b2 (float4 LDS) --------------
__global__ __launch_bounds__(256) void k3_gemm2(const float* __restrict__ W2,
                                                const float* __restrict__ b2) {
    __shared__ float h1s[16][256];
    const int rb = blockIdx.x * 16;
    const int tid = threadIdx.x;
#pragma unroll 4
    for (int r = 0; r < 16; r++) {
        float v = g_a1[(rb + r) * 256 + tid] * g_sc1[tid] + g_sh1[tid];
        h1s[r][tid] = fmaxf(v, 0.0f);
    }
    __syncthreads();
    const int c  = tid & 63;
    const int rq = tid >> 6;
    float acc[4] = {0.f, 0.f, 0.f, 0.f};
    for (int k = 0; k < 256; k += 4) {
        float w0 = W2[(k + 0) * 64 + c];
        float w1 = W2[(k + 1) * 64 + c];
        float w2v = W2[(k + 2) * 64 + c];
        float w3v = W2[(k + 3) * 64 + c];
#pragma unroll
        for (int i = 0; i < 4; i++) {
            float4 h = *reinterpret_cast<const float4*>(&h1s[rq * 4 + i][k]);
            acc[i] = fmaf(h.x, w0, acc[i]);
            acc[i] = fmaf(h.y, w1, acc[i]);
            acc[i] = fmaf(h.z, w2v, acc[i]);
            acc[i] = fmaf(h.w, w3v, acc[i]);
        }
    }
#pragma unroll
    for (int i = 0; i < 4; i++)
        g_a2[(rb + rq * 4 + i) * 64 + c] = acc[i] + b2[c];
}

// ---------------- K5: tf32 tensor-core logits + bounded-gumbel argmax -------
// 128 blocks x 64 rows. 8 warps = 8 n-subtiles of the 64-feature tile.
// A (h2, tf32) lives in registers for the whole feature loop. W3 tile is
// double-buffered via register prefetch; smem W padded to stride 72 so the
// B-fragment LDS pattern (bank = 8*(t%4)+t/4) is conflict-free.
__global__ __launch_bounds__(256, 1) void k5_mma(const float* __restrict__ W3,
                                                 const float* __restrict__ b3) {
    extern __shared__ char sm_[];
    float*    h2f  = (float*)sm_;                    // [64][68]
    float*    ws   = h2f + 64 * 68;                  // [64][72]
    int*      cand = (int*)(ws + 64 * 72);           // [64][CAP]
    unsigned* rmx  = (unsigned*)(cand + 64 * CAP);   // [64]
    int*      scnt = (int*)(rmx + 64);               // [64]

    const int tid = threadIdx.x, lane = tid & 31, wid = tid >> 5;
    const int rb = blockIdx.x * 64;

    for (int i = tid; i < 64 * 64; i += 256) {
        int r = i >> 6, k = i & 63;
        float v = g_a2[(rb + r) * 64 + k] * g_sc2[k] + g_sh2[k];
        h2f[r * 68 + k] = fmaxf(v, 0.0f);
    }
    if (tid < 64) { rmx[tid] = encf(-1e30f); scnt[tid] = 0; }
    __syncthreads();

    const int g  = lane >> 2;   // group id 0..7
    const int c4 = lane & 3;    // thread-in-group

    // A fragments (tf32) in registers: [msub][kstep][4]
    unsigned au[4][8][4];
#pragma unroll
    for (int m = 0; m < 4; m++)
#pragma unroll
        for (int k = 0; k < 8; k++) {
            int r0 = m * 16 + g, c0 = k * 8 + c4;
            au[m][k][0] = cvt_tf32(h2f[r0 * 68 + c0]);
            au[m][k][1] = cvt_tf32(h2f[(r0 + 8) * 68 + c0]);
            au[m][k][2] = cvt_tf32(h2f[r0 * 68 + c0 + 4]);
            au[m][k][3] = cvt_tf32(h2f[(r0 + 8) * 68 + c0 + 4]);
        }

    // stage W tile 0
    float4 pre[4];
#pragma unroll
    for (int it = 0; it < 4; it++) {
        int r = (tid >> 4) + it * 16, q = tid & 15;
        pre[it] = *reinterpret_cast<const float4*>(W3 + r * FN + q * 4);
    }
#pragma unroll
    for (int it = 0; it < 4; it++) {
        int r = (tid >> 4) + it * 16, q = tid & 15;
        float4 p = pre[it];
        ws[r * 72 + q * 4 + 0] = tf32f(p.x);
        ws[r * 72 + q * 4 + 1] = tf32f(p.y);
        ws[r * 72 + q * 4 + 2] = tf32f(p.z);
        ws[r * 72 + q * 4 + 3] = tf32f(p.w);
    }
    __syncthreads();

    for (int t = 0; t < 128; t++) {
        const int f0 = t * 64;
        if (t + 1 < 128) {
#pragma unroll
            for (int it = 0; it < 4; it++) {
                int r = (tid >> 4) + it * 16, q = tid & 15;
                pre[it] = *reinterpret_cast<const float4*>(W3 + r * FN + f0 + 64 + q * 4);
            }
        }
        float acc[4][4];
#pragma unroll
        for (int m = 0; m < 4; m++) { acc[m][0] = acc[m][1] = acc[m][2] = acc[m][3] = 0.f; }
#pragma unroll
        for (int k = 0; k < 8; k++) {
            unsigned b0 = __float_as_uint(ws[(k * 8 + c4) * 72 + wid * 8 + g]);
            unsigned b1 = __float_as_uint(ws[(k * 8 + c4 + 4) * 72 + wid * 8 + g]);
#pragma unroll
            for (int m = 0; m < 4; m++) mma_tf32(acc[m], au[m][k], b0, b1);
        }
        const int fc = f0 + wid * 8 + c4 * 2;
        const float bf0 = b3[fc], bf1 = b3[fc + 1];
        // phase 1: row maxima
#pragma unroll
        for (int m = 0; m < 4; m++) {
            acc[m][0] += bf0; acc[m][1] += bf1; acc[m][2] += bf0; acc[m][3] += bf1;
            float mlo = fmaxf(acc[m][0], acc[m][1]);
            float mhi = fmaxf(acc[m][2], acc[m][3]);
            mlo = fmaxf(mlo, __shfl_xor_sync(0xFFFFFFFFu, mlo, 1));
            mlo = fmaxf(mlo, __shfl_xor_sync(0xFFFFFFFFu, mlo, 2));
            mhi = fmaxf(mhi, __shfl_xor_sync(0xFFFFFFFFu, mhi, 1));
            mhi = fmaxf(mhi, __shfl_xor_sync(0xFFFFFFFFu, mhi, 2));
            if (c4 == 0) {
                int rlo = m * 16 + g, rhi = rlo + 8;
                unsigned ne = encf(mlo);
                if (ne > rmx[rlo]) atomicMax(&rmx[rlo], ne);
                ne = encf(mhi);
                if (ne > rmx[rhi]) atomicMax(&rmx[rhi], ne);
            }
        }
        __syncthreads();
        // phase 2: candidate append (superset: running max <= final max)
#pragma unroll
        for (int m = 0; m < 4; m++) {
            int rlo = m * 16 + g, rhi = rlo + 8;
            float tlo = decf(rmx[rlo]) - MARGIN;
            float thi = decf(rmx[rhi]) - MARGIN;
            if (acc[m][0] > tlo) { int p = atomicAdd(&scnt[rlo], 1); if (p < CAP) cand[rlo * CAP + p] = fc; }
            if (acc[m][1] > tlo) { int p = atomicAdd(&scnt[rlo], 1); if (p < CAP) cand[rlo * CAP + p] = fc + 1; }
            if (acc[m][2] > thi) { int p = atomicAdd(&scnt[rhi], 1); if (p < CAP) cand[rhi * CAP + p] = fc; }
            if (acc[m][3] > thi) { int p = atomicAdd(&scnt[rhi], 1); if (p < CAP) cand[rhi * CAP + p] = fc + 1; }
        }
        if (t + 1 < 128) {
#pragma unroll
            for (int it = 0; it < 4; it++) {
                int r = (tid >> 4) + it * 16, q = tid & 15;
                float4 p = pre[it];
                ws[r * 72 + q * 4 + 0] = tf32f(p.x);
                ws[r * 72 + q * 4 + 1] = tf32f(p.y);
                ws[r * 72 + q * 4 + 2] = tf32f(p.z);
                ws[r * 72 + q * 4 + 3] = tf32f(p.w);
            }
        }
        __syncthreads();
    }

    // exact refine: warp w owns rows w, w+8, ...
    for (int rr = wid; rr < 64; rr += 8) {
        const int row = rb + rr;
        const int c = scnt[rr];
        float bestv = -1e30f; int bestf = 0x7FFFFFFF;
        if (c <= CAP) {
            for (int i = lane; i < c; i += 32) {
                int f = cand[rr * CAP + i];
                float dot = 0.f;
#pragma unroll
                for (int k = 0; k < 64; k++)
                    dot = fmaf(h2f[rr * 68 + k], W3[k * FN + f], dot);
                float logit = __fadd_rn(dot, b3[f]);
                float gg = gumbel_ref(jax_bits((unsigned)row * 8192u + (unsigned)f));
                float v = __fdiv_rn(__fadd_rn(logit, gg), 0.1f);
                if (v > bestv || (v == bestv && f < bestf)) { bestv = v; bestf = f; }
            }
        } else {   // overflow fallback: exact full-row scan with cheap filter
            float th = decf(rmx[rr]) - MARGIN;
            for (int f = lane; f < FN; f += 32) {
                float dot = 0.f;
#pragma unroll
                for (int k = 0; k < 64; k++)
                    dot = fmaf(h2f[rr * 68 + k], W3[k * FN + f], dot);
                float logit = __fadd_rn(dot, b3[f]);
                if (logit > th) {
                    float gg = gumbel_ref(jax_bits((unsigned)row * 8192u + (unsigned)f));
                    float v = __fdiv_rn(__fadd_rn(logit, gg), 0.1f);
                    if (v > bestv || (v == bestv && f < bestf)) { bestv = v; bestf = f; }
                }
            }
        }
#pragma unroll
        for (int off = 16; off > 0; off >>= 1) {
            float ov = __shfl_xor_sync(0xFFFFFFFFu, bestv, off);
            int   of = __shfl_xor_sync(0xFFFFFFFFu, bestf, off);
            if (ov > bestv || (ov == bestv && of < bestf)) { bestv = ov; bestf = of; }
        }
        if (lane == 0) g_ind[row] = bestf;
    }
}

// ---------------- K7: out[row] = codebook[ind[row]] -------------------------
__global__ void k7_gather(const float* __restrict__ codebook, float* __restrict__ out) {
    const int row = blockIdx.x;
    const int ind = g_ind[row];
    const float4* src = reinterpret_cast<const float4*>(codebook + (size_t)ind * DN);
    float4* dst = reinterpret_cast<float4*>(out + (size_t)row * DN);
    dst[threadIdx.x] = src[threadIdx.x];
}

// ---------------- launch ----------------------------------------------------
extern "C" void kernel_launch(void* const* d_in, const int* in_sizes, int n_in,
                              void* d_out, int out_size) {
    const float* x   = (const float*)d_in[0];
    const float* y   = (const float*)d_in[1];
    const float* W1  = (const float*)d_in[2];
    const float* b1  = (const float*)d_in[3];
    const float* g1  = (const float*)d_in[4];
    const float* be1 = (const float*)d_in[5];
    const float* W2  = (const float*)d_in[6];
    const float* b2  = (const float*)d_in[7];
    const float* g2  = (const float*)d_in[8];
    const float* be2 = (const float*)d_in[9];
    const float* W3  = (const float*)d_in[10];
    const float* b3  = (const float*)d_in[11];
    const float* cb  = (const float*)d_in[12];
    float* out = (float*)d_out;

    const int smem5 = (64 * 68 + 64 * 72 + 64 * CAP + 128) * 4;
    static int attr_set = 0;
    if (!attr_set) {
        cudaFuncSetAttribute(k5_mma, cudaFuncAttributeMaxDynamicSharedMemorySize, smem5);
        attr_set = 1;
    }

    k1_gemm1<<<BN / 8, 256>>>(x, y, W1, b1);
    kstats1<<<64, 256>>>(0);
    kstats2<<<1, H1N>>>(0, g1, be1);
    k3_gemm2<<<BN / 16, 256>>>(W2, b2);
    kstats1<<<64, 256>>>(1);
    kstats2<<<1, H2N>>>(1, g2, be2);
    k5_mma<<<BN / 64, 256, smem5>>>(W3, b3);
    k7_gather<<<BN, 256>>>(cb, out);
}